// round 5
// baseline (speedup 1.0000x reference)
#include <cuda_runtime.h>
#include <math_constants.h>

#define NCH   64
#define NPIX  16384      // 128*128
#define BINS  256
#define SEGS  4          // blocks per channel in loss kernel

__device__ float g_cdf[NCH][BINS];
__device__ float g_minx[NCH];
__device__ float g_stepx[NCH];
__device__ float g_mask_sum;
__device__ float g_sumsq;

__device__ __forceinline__ float warpSum(float v){
    #pragma unroll
    for (int o = 16; o; o >>= 1) v += __shfl_down_sync(0xffffffffu, v, o);
    return v;
}
__device__ __forceinline__ float warpMin(float v){
    #pragma unroll
    for (int o = 16; o; o >>= 1) v = fminf(v, __shfl_down_sync(0xffffffffu, v, o));
    return v;
}
__device__ __forceinline__ float warpMax(float v){
    #pragma unroll
    for (int o = 16; o; o >>= 1) v = fmaxf(v, __shfl_down_sync(0xffffffffu, v, o));
    return v;
}

// K1: per-channel stats + histogram + cdf. One block per channel, 256 threads.
__global__ void __launch_bounds__(256) k_stats(
    const float* __restrict__ input,
    const float* __restrict__ match,
    const float* __restrict__ mask)
{
    const int c = blockIdx.x;
    const int t = threadIdx.x;
    const float* __restrict__ mch = match + c * NPIX;
    const float* __restrict__ inp = input + c * NPIX;

    float mnM =  CUDART_INF_F, mxM = -CUDART_INF_F;
    float mnX =  CUDART_INF_F, mxX = -CUDART_INF_F;
    float msum = 0.f;

    #pragma unroll 4
    for (int i = t; i < NPIX; i += 256) {
        float mk = mask[i];
        float vm = mch[i] * mk;
        float vx = inp[i] * mk;
        mnM = fminf(mnM, vm);  mxM = fmaxf(mxM, vm);
        mnX = fminf(mnX, vx);  mxX = fmaxf(mxX, vx);
        msum += mk;
    }

    __shared__ float sred[8][5];
    const int lane = t & 31, w = t >> 5;
    mnM = warpMin(mnM);  mxM = warpMax(mxM);
    mnX = warpMin(mnX);  mxX = warpMax(mxX);
    msum = warpSum(msum);
    if (lane == 0) {
        sred[w][0] = mnM; sred[w][1] = mxM;
        sred[w][2] = mnX; sred[w][3] = mxX;
        sred[w][4] = msum;
    }
    __syncthreads();

    __shared__ float sbc[2];      // [0]=mn_match, [1]=safe bin width
    __shared__ int   hist[BINS];
    hist[t] = 0;                  // concurrent with t==0 work below; different arrays

    if (t == 0) {
        float a = sred[0][0], b = sred[0][1];
        float d = sred[0][2], e = sred[0][3];
        float f = sred[0][4];
        #pragma unroll
        for (int i = 1; i < 8; i++) {
            a = fminf(a, sred[i][0]); b = fmaxf(b, sred[i][1]);
            d = fminf(d, sred[i][2]); e = fmaxf(e, sred[i][3]);
            f += sred[i][4];
        }
        float wM = (b - a) / (float)BINS;             // histc bin width
        sbc[0] = a;
        sbc[1] = (wM > 0.f) ? wM : 1.0f;              // safe_w semantics
        g_minx[c]  = d;
        g_stepx[c] = (e - d) / (float)BINS;           // remap step
        if (c == 0) { g_mask_sum = f; g_sumsq = 0.f; }
    }
    __syncthreads();

    // Pass 2: histogram of match*mask with torch.histc semantics
    const float mn = sbc[0], wS = sbc[1];
    #pragma unroll 4
    for (int i = t; i < NPIX; i += 256) {
        float vm = mch[i] * mask[i];
        int b = (int)floorf((vm - mn) / wS);
        b = min(BINS - 1, max(0, b));
        atomicAdd(&hist[b], 1);
    }
    __syncthreads();

    // Inclusive scan (cdf). Counts are exact integers; cumsum exact in fp32.
    __shared__ int sc[BINS];
    sc[t] = hist[t];
    __syncthreads();
    #pragma unroll
    for (int off = 1; off < BINS; off <<= 1) {
        int add = (t >= off) ? sc[t - off] : 0;
        __syncthreads();
        sc[t] += add;
        __syncthreads();
    }
    g_cdf[c][t] = (float)sc[t];
}

// K2: loss accumulation. SEGS blocks per channel, 256 threads each.
__global__ void __launch_bounds__(256) k_loss(
    const float* __restrict__ input,
    const float* __restrict__ mask)
{
    const int c   = blockIdx.x / SEGS;
    const int seg = blockIdx.x % SEGS;
    const int t   = threadIdx.x;

    __shared__ float cdf0[BINS], cdfc[BINS], r0[BINS];
    cdf0[t] = g_cdf[0][t];
    cdfc[t] = g_cdf[c][t];
    __syncthreads();

    // Build r0[j] for j = 0..255 from CHANNEL-0 quantities (faithful flattened-gather bug):
    // i0 = #{b : cdf0[b] < j+1}; ratio = clip((j+1 - cdf0[i0-1]) / (1e-8 + cdf0[i0]));
    // r0[j] = min0 + (ratio + i0) * step0
    {
        const float rank = (float)(t + 1);
        int lo = 0, hi = BINS;
        #pragma unroll
        for (int it = 0; it < 8; it++) {
            int mid = (lo + hi) >> 1;
            if (cdf0[mid] < rank) lo = mid + 1; else hi = mid;
        }
        const int i0 = lo;                       // in [0, 255]
        const float prev  = i0 ? cdf0[i0 - 1] : 0.f;
        float ratio = (rank - prev) / (1e-8f + cdf0[i0]);
        ratio = fminf(1.f, fmaxf(0.f, ratio));
        r0[t] = g_minx[0] + (ratio + (float)i0) * g_stepx[0];
    }
    __syncthreads();

    const float* __restrict__ inp = input + c * NPIX;
    const int base = seg * (NPIX / SEGS);

    float acc = 0.f;
    #pragma unroll 4
    for (int k = 0; k < (NPIX / SEGS) / 256; k++) {
        const int n = base + k * 256 + t;
        const float rank = (float)(n + 1);
        int lo = 0, hi = BINS;
        #pragma unroll
        for (int it = 0; it < 8; it++) {
            int mid = (lo + hi) >> 1;
            if (cdfc[mid] < rank) lo = mid + 1; else hi = mid;
        }
        const float corr = r0[lo];               // gather from channel-0 correction row
        const float x = inp[n] * mask[n];
        const float d = corr - x;
        acc += d * d;
    }

    acc = warpSum(acc);
    __shared__ float sw[8];
    if ((t & 31) == 0) sw[t >> 5] = acc;
    __syncthreads();
    if (t == 0) {
        float s = 0.f;
        #pragma unroll
        for (int i = 0; i < 8; i++) s += sw[i];
        atomicAdd(&g_sumsq, s);
    }
}

// K3: finalize scalar loss
__global__ void k_final(float* __restrict__ out)
{
    const float size = (float)(NCH * NPIX);
    float mean = g_sumsq / size;
    out[0] = mean * g_mask_sum * (float)NCH / size;   // * WEIGHT (=1.0)
}

extern "C" void kernel_launch(void* const* d_in, const int* in_sizes, int n_in,
                              void* d_out, int out_size)
{
    const float* input = (const float*)d_in[0];
    const float* match = (const float*)d_in[1];
    const float* mask  = (const float*)d_in[2];
    // d_in[3] = bins (256), compile-time constant here

    k_stats<<<NCH, 256>>>(input, match, mask);
    k_loss <<<NCH * SEGS, 256>>>(input, mask);
    k_final<<<1, 1>>>((float*)d_out);
}

// round 7
// speedup vs baseline: 1.4403x; 1.4403x over previous
#include <cuda_runtime.h>
#include <math_constants.h>

#define NCH   64
#define NPIX  16384      // 128*128
#define BINS  256
#define MSEG  4          // blocks per channel in min/max kernel
#define HSEG  4          // blocks per channel in histogram kernel
#define LSEG  8          // blocks per channel in loss kernel
#define SLICE_M (NPIX / MSEG)   // 4096
#define SLICE_H (NPIX / HSEG)   // 4096
#define SLICE_L (NPIX / LSEG)   // 2048

// Atomic-free partials
__device__ float g_mmM[NCH][MSEG][2];     // match*mask {min,max} partials
__device__ float g_x0mn[MSEG];            // input ch0 * mask min partials
__device__ float g_x0mx[MSEG];            // input ch0 * mask max partials
__device__ float g_msum[MSEG];            // mask sum partials
__device__ int   g_histp[NCH][HSEG][BINS];
__device__ float g_ls[NCH * LSEG];        // per-block loss partials

__device__ __forceinline__ float warpSum(float v){
    #pragma unroll
    for (int o = 16; o; o >>= 1) v += __shfl_down_sync(0xffffffffu, v, o);
    return v;
}
__device__ __forceinline__ float warpMin(float v){
    #pragma unroll
    for (int o = 16; o; o >>= 1) v = fminf(v, __shfl_down_sync(0xffffffffu, v, o));
    return v;
}
__device__ __forceinline__ float warpMax(float v){
    #pragma unroll
    for (int o = 16; o; o >>= 1) v = fmaxf(v, __shfl_down_sync(0xffffffffu, v, o));
    return v;
}

// ───────────────────────── K1: min/max partials ─────────────────────────
// grid = NCH*MSEG, block = 256. float4 loads, no atomics.
__global__ void __launch_bounds__(256) k_mm(
    const float* __restrict__ input,
    const float* __restrict__ match,
    const float* __restrict__ mask)
{
    const int c   = blockIdx.x / MSEG;
    const int seg = blockIdx.x % MSEG;
    const int t   = threadIdx.x;
    const int base = seg * SLICE_M;

    const float4* __restrict__ m4 = (const float4*)(match + c * NPIX + base);
    const float4* __restrict__ k4 = (const float4*)(mask + base);
    const float4* __restrict__ x4 = (const float4*)(input + base);   // channel 0

    float mnM =  CUDART_INF_F, mxM = -CUDART_INF_F;
    float mnX =  CUDART_INF_F, mxX = -CUDART_INF_F;
    float ms  = 0.f;

    #pragma unroll
    for (int k = 0; k < SLICE_M / (256 * 4); k++) {
        const int i = t + 256 * k;
        float4 a = m4[i], b = k4[i];
        float p0 = a.x * b.x, p1 = a.y * b.y, p2 = a.z * b.z, p3 = a.w * b.w;
        mnM = fminf(fminf(mnM, p0), fminf(p1, fminf(p2, p3)));
        mxM = fmaxf(fmaxf(mxM, p0), fmaxf(p1, fmaxf(p2, p3)));
        if (c == 0) {
            float4 xv = x4[i];
            float q0 = xv.x * b.x, q1 = xv.y * b.y, q2 = xv.z * b.z, q3 = xv.w * b.w;
            mnX = fminf(fminf(mnX, q0), fminf(q1, fminf(q2, q3)));
            mxX = fmaxf(fmaxf(mxX, q0), fmaxf(q1, fmaxf(q2, q3)));
            ms += (b.x + b.y) + (b.z + b.w);
        }
    }

    __shared__ float sred[8][5];
    const int lane = t & 31, w = t >> 5;
    mnM = warpMin(mnM);  mxM = warpMax(mxM);
    mnX = warpMin(mnX);  mxX = warpMax(mxX);
    ms  = warpSum(ms);
    if (lane == 0) {
        sred[w][0] = mnM; sred[w][1] = mxM;
        sred[w][2] = mnX; sred[w][3] = mxX;
        sred[w][4] = ms;
    }
    __syncthreads();
    if (t == 0) {
        float a = sred[0][0], b = sred[0][1];
        float d = sred[0][2], e = sred[0][3];
        float f = sred[0][4];
        #pragma unroll
        for (int i = 1; i < 8; i++) {
            a = fminf(a, sred[i][0]); b = fmaxf(b, sred[i][1]);
            d = fminf(d, sred[i][2]); e = fmaxf(e, sred[i][3]);
            f += sred[i][4];
        }
        g_mmM[c][seg][0] = a;
        g_mmM[c][seg][1] = b;
        if (c == 0) { g_x0mn[seg] = d; g_x0mx[seg] = e; g_msum[seg] = f; }
    }
}

// ───────────────────────── K2: histogram partials ─────────────────────────
// grid = NCH*HSEG, block = 256. Private smem hist → per-segment global (no atomics on gmem).
__global__ void __launch_bounds__(256) k_hist(
    const float* __restrict__ match,
    const float* __restrict__ mask)
{
    const int c   = blockIdx.x / HSEG;
    const int seg = blockIdx.x % HSEG;
    const int t   = threadIdx.x;

    __shared__ int   h[BINS];
    __shared__ float sbc[2];    // mn, safe width
    h[t] = 0;
    if (t == 0) {
        float a = g_mmM[c][0][0], b = g_mmM[c][0][1];
        #pragma unroll
        for (int i = 1; i < MSEG; i++) {
            a = fminf(a, g_mmM[c][i][0]);
            b = fmaxf(b, g_mmM[c][i][1]);
        }
        float wM = (b - a) / (float)BINS;
        sbc[0] = a;
        sbc[1] = (wM > 0.f) ? wM : 1.0f;
    }
    __syncthreads();
    const float mn = sbc[0], wS = sbc[1];

    const int base = seg * SLICE_H;
    const float4* __restrict__ m4 = (const float4*)(match + c * NPIX + base);
    const float4* __restrict__ k4 = (const float4*)(mask + base);

    #pragma unroll
    for (int k = 0; k < SLICE_H / (256 * 4); k++) {
        const int i = t + 256 * k;
        float4 a = m4[i], b = k4[i];
        float p[4] = {a.x * b.x, a.y * b.y, a.z * b.z, a.w * b.w};
        #pragma unroll
        for (int j = 0; j < 4; j++) {
            int bi = (int)floorf((p[j] - mn) / wS);
            bi = min(BINS - 1, max(0, bi));
            atomicAdd(&h[bi], 1);
        }
    }
    __syncthreads();
    g_histp[c][seg][t] = h[t];
}

// ───────────────────────── K3: loss ─────────────────────────
// grid = NCH*LSEG, block = 256.
__global__ void __launch_bounds__(256) k_loss(
    const float* __restrict__ input,
    const float* __restrict__ mask)
{
    const int c   = blockIdx.x / LSEG;
    const int seg = blockIdx.x % LSEG;
    const int t   = threadIdx.x;

    __shared__ float cdf0[BINS], cdfc[BINS], r0[BINS];
    __shared__ float sbc[2];   // min0, step0 (channel-0 input stats)

    // Sum hist partials for channel 0 and channel c
    float v0 = 0.f, vc = 0.f;
    #pragma unroll
    for (int i = 0; i < HSEG; i++) {
        v0 += (float)g_histp[0][i][t];
        vc += (float)g_histp[c][i][t];
    }
    cdf0[t] = v0;  cdfc[t] = vc;
    if (t == 0) {
        float d = g_x0mn[0], e = g_x0mx[0];
        #pragma unroll
        for (int i = 1; i < MSEG; i++) {
            d = fminf(d, g_x0mn[i]);
            e = fmaxf(e, g_x0mx[i]);
        }
        sbc[0] = d;
        sbc[1] = (e - d) / (float)BINS;
    }
    __syncthreads();

    // Inclusive scan of both arrays (counts are exact integers in fp32)
    #pragma unroll
    for (int off = 1; off < BINS; off <<= 1) {
        float a0 = (t >= off) ? cdf0[t - off] : 0.f;
        float ac = (t >= off) ? cdfc[t - off] : 0.f;
        __syncthreads();
        cdf0[t] += a0;  cdfc[t] += ac;
        __syncthreads();
    }

    // Build r0[j] from CHANNEL-0 quantities (faithful flattened-gather semantics)
    {
        const float rank = (float)(t + 1);
        int lo = 0, hi = BINS;
        #pragma unroll
        for (int it = 0; it < 8; it++) {
            int mid = (lo + hi) >> 1;
            if (cdf0[mid] < rank) lo = mid + 1; else hi = mid;
        }
        const float prev = lo ? cdf0[lo - 1] : 0.f;
        float ratio = (rank - prev) / (1e-8f + cdf0[lo]);
        ratio = fminf(1.f, fmaxf(0.f, ratio));
        r0[t] = sbc[0] + (ratio + (float)lo) * sbc[1];
    }
    __syncthreads();

    const int base = seg * SLICE_L;
    const float4* __restrict__ x4 = (const float4*)(input + c * NPIX + base);
    const float4* __restrict__ k4 = (const float4*)(mask + base);

    float acc = 0.f;
    #pragma unroll
    for (int k = 0; k < SLICE_L / (256 * 4); k++) {
        const int i = t + 256 * k;
        float4 xv = x4[i], mk = k4[i];
        const int n0 = base + i * 4;
        float xs[4] = {xv.x * mk.x, xv.y * mk.y, xv.z * mk.z, xv.w * mk.w};
        #pragma unroll
        for (int j = 0; j < 4; j++) {
            const float rank = (float)(n0 + j + 1);
            int lo = 0, hi = BINS;
            #pragma unroll
            for (int it = 0; it < 8; it++) {
                int mid = (lo + hi) >> 1;
                if (cdfc[mid] < rank) lo = mid + 1; else hi = mid;
            }
            const float d = r0[lo] - xs[j];
            acc += d * d;
        }
    }

    acc = warpSum(acc);
    __shared__ float sw[8];
    if ((t & 31) == 0) sw[t >> 5] = acc;
    __syncthreads();
    if (t == 0) {
        float s = 0.f;
        #pragma unroll
        for (int i = 0; i < 8; i++) s += sw[i];
        g_ls[blockIdx.x] = s;
    }
}

// ───────────────────────── K4: finalize ─────────────────────────
__global__ void __launch_bounds__(512) k_final(float* __restrict__ out)
{
    const int t = threadIdx.x;
    float v = g_ls[t];                        // NCH*LSEG == 512
    v = warpSum(v);
    __shared__ float sw[16];
    if ((t & 31) == 0) sw[t >> 5] = v;
    __syncthreads();
    if (t == 0) {
        float s = 0.f;
        #pragma unroll
        for (int i = 0; i < 16; i++) s += sw[i];
        float msum = 0.f;
        #pragma unroll
        for (int i = 0; i < MSEG; i++) msum += g_msum[i];
        const float size = (float)(NCH * NPIX);
        out[0] = (s / size) * msum * (float)NCH / size;   // * WEIGHT (=1.0)
    }
}

extern "C" void kernel_launch(void* const* d_in, const int* in_sizes, int n_in,
                              void* d_out, int out_size)
{
    const float* input = (const float*)d_in[0];
    const float* match = (const float*)d_in[1];
    const float* mask  = (const float*)d_in[2];

    k_mm   <<<NCH * MSEG, 256>>>(input, match, mask);
    k_hist <<<NCH * HSEG, 256>>>(match, mask);
    k_loss <<<NCH * LSEG, 256>>>(input, mask);
    k_final<<<1, 512>>>((float*)d_out);
}